// round 17
// baseline (speedup 1.0000x reference)
#include <cuda_runtime.h>
#include <cuda_bf16.h>
#include <math_constants.h>
#include <cstdint>

// Problem constants
#define NU   8192
#define NL   8192     // per half
#define DD   512
#define CC   1000
#define INV_TAU 10.0f

// ---------------- device scratch ---------------------------------------------
__device__ __nv_bfloat16 g_aqh [NU * DD];
__device__ __nv_bfloat16 g_pqh [NU * DD];
__device__ __nv_bfloat16 g_suph[2 * NL * DD];     // class-sorted order
__device__ float g_rowsum[2 * NU];
__device__ int   g_labels[2 * NL];
__device__ int   g_offsets[2 * (CC + 1)];
__device__ int   g_perm[2 * NL];

// ---------------- PTX helpers -------------------------------------------------
__device__ __forceinline__ uint32_t smem_u32(const void* p) {
    uint32_t a;
    asm("{ .reg .u64 t; cvta.to.shared.u64 t, %1; cvt.u32.u64 %0, t; }" : "=r"(a) : "l"(p));
    return a;
}
#define CP_ASYNC16(s, g) asm volatile("cp.async.cg.shared.global [%0], [%1], 16;" :: "r"(s), "l"(g))
#define CP_COMMIT()      asm volatile("cp.async.commit_group;" ::: "memory")
#define CP_WAIT(n)       asm volatile("cp.async.wait_group %0;" :: "n"(n) : "memory")

__device__ __forceinline__ void ldsm_x4(uint32_t* r, uint32_t addr) {
    asm volatile("ldmatrix.sync.aligned.m8n8.x4.shared.b16 {%0,%1,%2,%3}, [%4];"
        : "=r"(r[0]), "=r"(r[1]), "=r"(r[2]), "=r"(r[3]) : "r"(addr));
}
__device__ __forceinline__ void mma_bf16(float* c, const uint32_t* a, const uint32_t* b) {
    asm volatile("mma.sync.aligned.m16n8k16.row.col.f32.bf16.bf16.f32 "
        "{%0,%1,%2,%3},{%4,%5,%6,%7},{%8,%9},{%0,%1,%2,%3};"
        : "+f"(c[0]), "+f"(c[1]), "+f"(c[2]), "+f"(c[3])
        : "r"(a[0]), "r"(a[1]), "r"(a[2]), "r"(a[3]), "r"(b[0]), "r"(b[1]));
}

// ---- (1) heterogeneous prep: copies + labels + q-normalize + zeroing ---------
#define NB_OH 2048
#define NB_Q  2048
#define NL4 2097152u
#define NG4 4096000u
#define NZ4 4096000u
#define NR4 4096u
#define NTOT4 (NL4 + NG4 + NZ4 + NR4)
#define NB_R  ((NTOT4 + 255) / 256)
#define NB_PREP (NB_OH + NB_Q + NB_R)

__global__ void __launch_bounds__(256) prep_k(
    const float* __restrict__ anchor, const float* __restrict__ pos,
    const float* __restrict__ lb, const float* __restrict__ oh,
    const float* __restrict__ lgx,
    float* __restrict__ outA, float* __restrict__ outP,
    float* __restrict__ outL, float* __restrict__ outOH,
    float* __restrict__ outLG, float* __restrict__ outU)
{
    const int tid  = threadIdx.x;
    uint32_t bid = blockIdx.x;

    if (bid < NB_OH) {
        int row  = bid * 8 + (tid >> 5);
        int lane = tid & 31;
        const float* r = oh + (size_t)row * CC;
        float* d = outOH + (size_t)row * CC;
        int lab = -1;
        for (int c = lane; c < CC; c += 32) {
            float v = r[c];
            d[c] = v;
            if (v > 0.5f) lab = c;
        }
        #pragma unroll
        for (int o = 16; o; o >>= 1) lab = max(lab, __shfl_xor_sync(0xffffffffu, lab, o));
        if (lane == 0) g_labels[row] = lab;
        return;
    }
    bid -= NB_OH;
    if (bid < NB_Q) {
        int sel  = bid >> 10;
        int row  = (bid & 1023) * 8 + (tid >> 5);
        int lane = tid & 31;
        const float* src = (sel == 0) ? anchor : pos;
        float* dstcopy   = (sel == 0) ? outA : outP;
        __nv_bfloat16* nb = ((sel == 0) ? g_aqh : g_pqh) + (size_t)row * DD;
        const float4* s4 = (const float4*)(src + (size_t)row * DD);
        float4* d4 = (float4*)(dstcopy + (size_t)row * DD);
        float4 v[4];
        float acc = 0.f;
        #pragma unroll
        for (int i = 0; i < 4; i++) {
            v[i] = s4[lane + 32 * i];
            acc += v[i].x * v[i].x + v[i].y * v[i].y + v[i].z * v[i].z + v[i].w * v[i].w;
        }
        #pragma unroll
        for (int o = 16; o; o >>= 1) acc += __shfl_xor_sync(0xffffffffu, acc, o);
        float inv = 1.0f / fmaxf(sqrtf(acc), 1e-12f);
        #pragma unroll
        for (int i = 0; i < 4; i++) {
            d4[lane + 32 * i] = v[i];
            int c = (lane + 32 * i) * 4;
            nb[c + 0] = __float2bfloat16(v[i].x * inv);
            nb[c + 1] = __float2bfloat16(v[i].y * inv);
            nb[c + 2] = __float2bfloat16(v[i].z * inv);
            nb[c + 3] = __float2bfloat16(v[i].w * inv);
        }
        return;
    }
    bid -= NB_Q;
    {
        uint32_t i = bid * 256 + tid;
        if (i >= NTOT4) return;
        if (i < NL4) { ((float4*)outL)[i] = ((const float4*)lb)[i]; return; }
        i -= NL4;
        if (i < NG4) { ((float4*)outLG)[i] = ((const float4*)lgx)[i]; return; }
        i -= NG4;
        float4 z = make_float4(0.f, 0.f, 0.f, 0.f);
        if (i < NZ4) { ((float4*)outU)[i] = z; return; }
        i -= NZ4;
        ((float4*)g_rowsum)[i] = z;
    }
}

// ---- (2) single-CTA counting sort: counts + scan + scatter -------------------
__global__ void __launch_bounds__(1024) sort_k() {
    __shared__ int cnt[CC];
    __shared__ int cur[CC + 1];
    __shared__ int ws[32];
    int tid = threadIdx.x;
    int h   = blockIdx.x;
    for (int c = tid; c < CC; c += 1024) cnt[c] = 0;
    __syncthreads();
    const int* lab = g_labels + h * NL;
    for (int i = tid; i < NL; i += 1024) atomicAdd(&cnt[lab[i]], 1);
    __syncthreads();
    int lane = tid & 31, wid = tid >> 5;
    int v = (tid < CC) ? cnt[tid] : 0;
    int x = v;
    #pragma unroll
    for (int o = 1; o < 32; o <<= 1) {
        int y = __shfl_up_sync(0xffffffffu, x, o);
        if (lane >= o) x += y;
    }
    if (lane == 31) ws[wid] = x;
    __syncthreads();
    if (wid == 0) {
        int s = ws[lane];
        #pragma unroll
        for (int o = 1; o < 32; o <<= 1) {
            int y = __shfl_up_sync(0xffffffffu, s, o);
            if (lane >= o) s += y;
        }
        ws[lane] = s;
    }
    __syncthreads();
    int excl = x - v + (wid > 0 ? ws[wid - 1] : 0);
    if (tid < CC) {
        g_offsets[h * (CC + 1) + tid] = excl;
        cur[tid] = excl;
    }
    if (tid == CC) g_offsets[h * (CC + 1) + CC] = excl;
    __syncthreads();
    int* perm = g_perm + h * NL;
    for (int i = tid; i < NL; i += 1024) {
        int pos = atomicAdd(&cur[lab[i]], 1);
        perm[pos] = i;
    }
}

// ---- (3) supports: normalize, write in class-sorted (perm) order -------------
__global__ void norm_sup_k(const float* __restrict__ lb) {
    int row  = blockIdx.x * (blockDim.x >> 5) + (threadIdx.x >> 5);
    int lane = threadIdx.x & 31;
    if (row >= 2 * NL) return;
    int half = row / NL;
    int pos  = row - half * NL;
    int srow = half * NL + g_perm[half * NL + pos];
    const float* s = lb + (size_t)srow * DD;
    float v[16];
    float acc = 0.f;
    #pragma unroll
    for (int i = 0; i < 16; i++) { v[i] = s[lane + 32 * i]; acc += v[i] * v[i]; }
    #pragma unroll
    for (int o = 16; o; o >>= 1) acc += __shfl_xor_sync(0xffffffffu, acc, o);
    float inv = 1.0f / fmaxf(sqrtf(acc), 1e-12f);
    __nv_bfloat16* d = g_suph + (size_t)row * DD;
    #pragma unroll
    for (int i = 0; i < 16; i++) d[lane + 32 * i] = __float2bfloat16(v[i] * inv);
}

// ---- (4) GEMM 128x256x32 + exp + class partial-sum epilogue ------------------
// 16 warps as 4(row) x 4(col); each warp 32 rows x 64 cols.
#define BM 128
#define BN 256
#define BKK 32
#define STAGES 3
#define NKIT (DD / BKK)                 // 16
#define SROW 80
#define STAGE_ROWS (BM + BN)            // 384
#define STAGE_BYTES (STAGE_ROWS * SROW) // 30720
#define A_OFF 0
#define B_OFF (BM * SROW)               // 10240
#define EP_PITCH 257
#define C2C_OFF (BM * EP_PITCH * 4)     // 131584
#define GEMM_SMEM (C2C_OFF + 1024 + 64) // 132672  (>= STAGES*STAGE_BYTES = 92160)

__global__ void __launch_bounds__(512) gemm_fused_k(float* __restrict__ ulbbase) {
    extern __shared__ __align__(16) char smem[];
    const uint32_t sbase = smem_u32(smem);

    const int tid  = threadIdx.x;
    const int wid  = tid >> 5;
    const int lane = tid & 31;
    const int wr   = wid & 3;      // warp row: 4 x 32 rows
    const int wc   = wid >> 2;     // warp col: 4 x 64 cols

    const int z  = blockIdx.z;
    const __nv_bfloat16* A = (z == 0) ? g_aqh : g_pqh;
    const __nv_bfloat16* B = g_suph + (size_t)z * NL * DD;
    const int m0 = blockIdx.y * BM;
    const int n0 = blockIdx.x * BN;
    const __nv_bfloat16* Abase = A + (size_t)m0 * DD;
    const __nv_bfloat16* Bbase = B + (size_t)n0 * DD;

    // stage load: 384 rows x 4 chunks = 1536 chunks; 3 per thread
    float acc[2][8][4];
    #pragma unroll
    for (int mi = 0; mi < 2; mi++)
        #pragma unroll
        for (int ni = 0; ni < 8; ni++)
            #pragma unroll
            for (int q = 0; q < 4; q++) acc[mi][ni][q] = 0.f;

    auto PF = [&](int kcq, int st) {
        uint32_t sg = sbase + st * STAGE_BYTES;
        const __nv_bfloat16* Ak = Abase + kcq * BKK;
        const __nv_bfloat16* Bk = Bbase + kcq * BKK;
        #pragma unroll
        for (int p = 0; p < 3; p++) {
            int ch  = tid + p * 512;       // 0..1535
            int row = ch >> 2;
            int col = (ch & 3) * 8;
            if (row < BM) {
                CP_ASYNC16(sg + A_OFF + row * SROW + col * 2, Ak + (size_t)row * DD + col);
            } else {
                CP_ASYNC16(sg + B_OFF + (row - BM) * SROW + col * 2, Bk + (size_t)(row - BM) * DD + col);
            }
        }
    };

    #pragma unroll
    for (int s = 0; s < STAGES - 1; s++) { PF(s, s); CP_COMMIT(); }

    const uint32_t aOff = (uint32_t)(wr * 32 + (lane & 15)) * SROW + (lane >> 4) * 16;
    const uint32_t bOff = (uint32_t)(wc * 64 + (lane & 15)) * SROW + (lane >> 4) * 16;

    for (int kc = 0; kc < NKIT; kc++) {
        const int st = kc % STAGES;
        CP_WAIT(STAGES - 2);
        __syncthreads();

        const int pf = kc + STAGES - 1;
        if (pf < NKIT) PF(pf, pf % STAGES);
        CP_COMMIT();

        const uint32_t sA = sbase + st * STAGE_BYTES + A_OFF;
        const uint32_t sB = sbase + st * STAGE_BYTES + B_OFF;
        #pragma unroll
        for (int kk = 0; kk < 2; kk++) {
            uint32_t aF[2][4], bQ[4][4];
            #pragma unroll
            for (int mi = 0; mi < 2; mi++)
                ldsm_x4(aF[mi], sA + aOff + (uint32_t)mi * 16 * SROW + kk * 32);
            #pragma unroll
            for (int nj = 0; nj < 4; nj++)
                ldsm_x4(bQ[nj], sB + bOff + (uint32_t)nj * 16 * SROW + kk * 32);
            #pragma unroll
            for (int mi = 0; mi < 2; mi++) {
                #pragma unroll
                for (int nj = 0; nj < 4; nj++) {
                    uint32_t b0[2] = { bQ[nj][0], bQ[nj][2] };
                    uint32_t b1[2] = { bQ[nj][1], bQ[nj][3] };
                    mma_bf16(acc[mi][2 * nj + 0], aF[mi], b0);
                    mma_bf16(acc[mi][2 * nj + 1], aF[mi], b1);
                }
            }
        }
    }

    // ---- epilogue: exp -> smem, per-row contiguous segment sums, atomics ----
    CP_WAIT(0);
    __syncthreads();

    float* ep    = (float*)smem;                 // 128 x 257
    int*   c2c_s = (int*)(smem + C2C_OFF);       // 256 ints

    const int ebr = wr * 32 + (lane >> 2);
    const int ebc = wc * 64 + (lane & 3) * 2;
    #pragma unroll
    for (int mi = 0; mi < 2; mi++) {
        #pragma unroll
        for (int ni = 0; ni < 8; ni++) {
            int rr = ebr + mi * 16, cc2 = ebc + ni * 8;
            ep[rr * EP_PITCH + cc2]           = __expf(acc[mi][ni][0] * INV_TAU);
            ep[rr * EP_PITCH + cc2 + 1]       = __expf(acc[mi][ni][1] * INV_TAU);
            ep[(rr + 8) * EP_PITCH + cc2]     = __expf(acc[mi][ni][2] * INV_TAU);
            ep[(rr + 8) * EP_PITCH + cc2 + 1] = __expf(acc[mi][ni][3] * INV_TAU);
        }
    }
    if (tid < BN) {
        const int* offs = g_offsets + z * (CC + 1);
        int v = n0 + tid;
        int lo = 0, hi = CC - 1;
        while (lo < hi) { int mid = (lo + hi + 1) >> 1; if (offs[mid] <= v) lo = mid; else hi = mid - 1; }
        c2c_s[tid] = lo;
    }
    __syncthreads();

    if (tid < BM) {
        float* orow = ulbbase + (size_t)z * NU * CC + (size_t)(m0 + tid) * CC;
        const float* er = ep + tid * EP_PITCH;
        float run = 0.f, rs = 0.f;
        int cls = c2c_s[0];
        #pragma unroll 4
        for (int j = 0; j < BN; j++) {
            int c2 = c2c_s[j];
            float e = er[j];
            if (c2 != cls) { atomicAdd(&orow[cls], run); run = 0.f; cls = c2; }
            run += e;
            rs  += e;
        }
        atomicAdd(&orow[cls], run);
        atomicAdd(&g_rowsum[z * NU + m0 + tid], rs);
    }
}

// ---- (5) normalize + zero empty classes --------------------------------------
__global__ void __launch_bounds__(256) normalize_k(float* __restrict__ ulbbase) {
    int u = blockIdx.x;
    int z = blockIdx.y;
    float inv = 1.0f / g_rowsum[z * NU + u];
    const int* offs = g_offsets + z * (CC + 1);
    float* orow = ulbbase + (size_t)z * NU * CC + (size_t)u * CC;
    for (int c = threadIdx.x; c < CC; c += 256) {
        float v = orow[c];
        orow[c] = (offs[c + 1] > offs[c]) ? v * inv : 0.f;
    }
}

// ---------------- launch ------------------------------------------------------
extern "C" void kernel_launch(void* const* d_in, const int* in_sizes, int n_in,
                              void* d_out, int out_size) {
    const float* anchor = (const float*)d_in[0];
    const float* pos    = (const float*)d_in[1];
    const float* lb     = (const float*)d_in[2];
    const float* oh     = (const float*)d_in[3];
    const float* lgx    = (const float*)d_in[4];
    float* out = (float*)d_out;

    const size_t nA  = (size_t)NU * DD;
    const size_t nP  = (size_t)NU * DD;
    const size_t nL  = (size_t)2 * NL * DD;
    const size_t nOH = (size_t)2 * NL * CC;
    const size_t nLG = (size_t)2 * NL * CC;
    size_t oA  = 0;
    size_t oP  = oA + nA;
    size_t oL  = oP + nP;
    size_t oOH = oL + nL;
    size_t oLG = oOH + nOH;
    size_t oU1 = oLG + nLG;

    // (1) mega prep
    prep_k<<<NB_PREP, 256>>>(anchor, pos, lb, oh, lgx,
                             out + oA, out + oP, out + oL, out + oOH,
                             out + oLG, out + oU1);
    // (2) counting sort
    sort_k<<<2, 1024>>>();
    // (3) supports normalize (class-sorted)
    norm_sup_k<<<(2 * NL) / 8, 256>>>(lb);
    // (4) GEMM 128x256 with fused epilogue
    cudaFuncSetAttribute(gemm_fused_k, cudaFuncAttributeMaxDynamicSharedMemorySize, GEMM_SMEM);
    dim3 gg(NL / BN, NU / BM, 2);
    gemm_fused_k<<<gg, 512, GEMM_SMEM>>>(out + oU1);
    // (5) normalize + zero empty classes
    dim3 gn(NU, 2);
    normalize_k<<<gn, 256>>>(out + oU1);
}